// round 1
// baseline (speedup 1.0000x reference)
#include <cuda_runtime.h>
#include <math.h>

// Problem constants
#define B_IMG 64
#define CH    3
#define IMG   224
#define PATCH 16
#define HID   384
#define PW    14
#define HW    196                 // 14*14 patches per image
#define M_TOT (B_IMG * HW)        // 12544 patches per tensor
#define K_PE  768                 // 3*16*16
#define KROW  (HW * HID)          // 75264 = per-image flattened row for CE gemm

// Scratch (device globals — no allocation allowed)
__device__ float g_emb[2u * M_TOT * HID]; // [0..): xp logits, [M_TOT*HID..): yp logits -> q (in-place)
__device__ float g_T[64 * 64];            // T = XP * Q^T partial sums (atomic split-K)
__device__ float g_S[64];                 // S_i = sum_hw lse_x[i,hw]

// ---------------------------------------------------------------------------
// init: zero accumulators (must re-zero on every launch: deterministic)
// ---------------------------------------------------------------------------
__global__ void k_init() {
    int t = blockIdx.x * blockDim.x + threadIdx.x;
    if (t < 64 * 64) g_T[t] = 0.0f;
    if (t < 64)      g_S[t] = 0.0f;
}

// ---------------------------------------------------------------------------
// Patch-embed GEMM:  out[m, n] = sum_k im2col[m, k] * W[n, k] + bias[n]
// m = (b, ph, pw), k = (c, r, s), n = channel.   M=12544, N=384, K=768.
// Block tile 64x64, BK=16 (one BK tile == one contiguous 16-float patch row),
// 256 threads, 4x4 microtile per thread. blockIdx.z selects x vs y.
// ---------------------------------------------------------------------------
__global__ void __launch_bounds__(256, 6)
k_patch_gemm(const float* __restrict__ x, const float* __restrict__ y,
             const float* __restrict__ W, const float* __restrict__ bias) {
    __shared__ float As[16][68];  // [k][m], pad to 68 (16B-aligned rows, fewer conflicts)
    __shared__ float Bs[16][68];  // [k][n]

    const float* im  = blockIdx.z ? y : x;
    float*       out = g_emb + (size_t)blockIdx.z * (M_TOT * HID);

    const int m0 = blockIdx.x * 64;
    const int n0 = blockIdx.y * 64;
    const int t  = threadIdx.x;
    const int lrow  = t >> 2;   // 0..63
    const int lquad = t & 3;    // 0..3  (which float4 along k within BK=16)

    // A-load addressing: patch (b, ph, pw) for row m0+lrow
    const int m   = m0 + lrow;
    const int b   = m / HW;
    const int rem = m - b * HW;
    const int ph  = rem / PW;
    const int pw  = rem - ph * PW;
    const float* abase = im + (size_t)b * (CH * IMG * IMG)
                            + (size_t)(ph * PATCH) * IMG + pw * PATCH + lquad * 4;
    // B-load addressing: W row n0+lrow (k contiguous, 768 floats)
    const float* wbase = W + (size_t)(n0 + lrow) * K_PE + lquad * 4;

    const int tx = t & 15;   // n microtile
    const int ty = t >> 4;   // m microtile
    float acc[4][4] = {};

    #pragma unroll 1
    for (int kt = 0; kt < K_PE / 16; ++kt) {
        const int k0 = kt * 16;
        const int c  = k0 >> 8;          // k0 / 256
        const int r  = (k0 & 255) >> 4;  // patch row within (c)
        const float4 av = *(const float4*)(abase + (size_t)c * (IMG * IMG) + r * IMG);
        const float4 bv = *(const float4*)(wbase + k0);

        __syncthreads();  // previous iteration done reading smem
        As[lquad * 4 + 0][lrow] = av.x;
        As[lquad * 4 + 1][lrow] = av.y;
        As[lquad * 4 + 2][lrow] = av.z;
        As[lquad * 4 + 3][lrow] = av.w;
        Bs[lquad * 4 + 0][lrow] = bv.x;
        Bs[lquad * 4 + 1][lrow] = bv.y;
        Bs[lquad * 4 + 2][lrow] = bv.z;
        Bs[lquad * 4 + 3][lrow] = bv.w;
        __syncthreads();

        #pragma unroll
        for (int k = 0; k < 16; ++k) {
            const float4 a4 = *(const float4*)&As[k][ty * 4];
            const float4 b4 = *(const float4*)&Bs[k][tx * 4];
            const float a[4] = {a4.x, a4.y, a4.z, a4.w};
            const float bb[4] = {b4.x, b4.y, b4.z, b4.w};
            #pragma unroll
            for (int ii = 0; ii < 4; ++ii)
                #pragma unroll
                for (int jj = 0; jj < 4; ++jj)
                    acc[ii][jj] = fmaf(a[ii], bb[jj], acc[ii][jj]);
        }
    }

    // Epilogue: add bias, write (m, n) tile
    const float4 bias4 = *(const float4*)(bias + n0 + tx * 4);
    const float bn[4] = {bias4.x, bias4.y, bias4.z, bias4.w};
    #pragma unroll
    for (int ii = 0; ii < 4; ++ii) {
        const int mm = m0 + ty * 4 + ii;
        float4 v;
        v.x = acc[ii][0] + bn[0];
        v.y = acc[ii][1] + bn[1];
        v.z = acc[ii][2] + bn[2];
        v.w = acc[ii][3] + bn[3];
        *(float4*)(out + (size_t)mm * HID + n0 + tx * 4) = v;
    }
}

// ---------------------------------------------------------------------------
// Per-row softmax pass. blockIdx.y == 0: xp rows -> accumulate lse into S[i].
// blockIdx.y == 1: yp rows -> overwrite with q = softmax(row) in place.
// 128 threads, 3 elements each (384 = 128*3).
// ---------------------------------------------------------------------------
__global__ void k_softmax() {
    const int row   = blockIdx.x;
    const int which = blockIdx.y;
    float* p = g_emb + (size_t)which * (M_TOT * HID) + (size_t)row * HID;
    const int t = threadIdx.x;

    float v0 = p[t], v1 = p[t + 128], v2 = p[t + 256];

    __shared__ float red[128];
    // max
    float mx = fmaxf(fmaxf(v0, v1), v2);
    red[t] = mx; __syncthreads();
    #pragma unroll
    for (int s = 64; s > 0; s >>= 1) {
        if (t < s) red[t] = fmaxf(red[t], red[t + s]);
        __syncthreads();
    }
    mx = red[0];
    __syncthreads();
    // sum of exp
    float e0 = expf(v0 - mx), e1 = expf(v1 - mx), e2 = expf(v2 - mx);
    red[t] = e0 + e1 + e2; __syncthreads();
    #pragma unroll
    for (int s = 64; s > 0; s >>= 1) {
        if (t < s) red[t] += red[t + s];
        __syncthreads();
    }
    const float sum = red[0];

    if (which == 1) {
        const float inv = 1.0f / sum;
        p[t]       = e0 * inv;
        p[t + 128] = e1 * inv;
        p[t + 256] = e2 * inv;
    } else {
        if (t == 0) atomicAdd(&g_S[row / HW], mx + logf(sum));
    }
}

// ---------------------------------------------------------------------------
// CE GEMM: T[i,j] += sum_k XP[i,k] * Q[j,k],  i,j in [0,64), K = 75264.
// Split-K: grid.x = 147 chunks of 512; atomicAdd epilogue into g_T.
// Same 64x64 / BK=16 / 4x4-per-thread scheme.
// ---------------------------------------------------------------------------
__global__ void __launch_bounds__(256, 6) k_ce_gemm() {
    __shared__ float As[16][68];
    __shared__ float Bs[16][68];

    const float* XP = g_emb;
    const float* Q  = g_emb + (size_t)M_TOT * HID;
    const int kbase = blockIdx.x * 512;

    const int t = threadIdx.x;
    const int lrow  = t >> 2;
    const int lquad = t & 3;
    const float* ap = XP + (size_t)lrow * KROW + kbase + lquad * 4;
    const float* bp = Q  + (size_t)lrow * KROW + kbase + lquad * 4;

    const int tx = t & 15;
    const int ty = t >> 4;
    float acc[4][4] = {};

    #pragma unroll 1
    for (int kt = 0; kt < 32; ++kt) {
        const float4 av = *(const float4*)(ap + kt * 16);
        const float4 bv = *(const float4*)(bp + kt * 16);
        __syncthreads();
        As[lquad * 4 + 0][lrow] = av.x;
        As[lquad * 4 + 1][lrow] = av.y;
        As[lquad * 4 + 2][lrow] = av.z;
        As[lquad * 4 + 3][lrow] = av.w;
        Bs[lquad * 4 + 0][lrow] = bv.x;
        Bs[lquad * 4 + 1][lrow] = bv.y;
        Bs[lquad * 4 + 2][lrow] = bv.z;
        Bs[lquad * 4 + 3][lrow] = bv.w;
        __syncthreads();
        #pragma unroll
        for (int k = 0; k < 16; ++k) {
            const float4 a4 = *(const float4*)&As[k][ty * 4];
            const float4 b4 = *(const float4*)&Bs[k][tx * 4];
            const float a[4]  = {a4.x, a4.y, a4.z, a4.w};
            const float bb[4] = {b4.x, b4.y, b4.z, b4.w};
            #pragma unroll
            for (int ii = 0; ii < 4; ++ii)
                #pragma unroll
                for (int jj = 0; jj < 4; ++jj)
                    acc[ii][jj] = fmaf(a[ii], bb[jj], acc[ii][jj]);
        }
    }

    #pragma unroll
    for (int ii = 0; ii < 4; ++ii)
        #pragma unroll
        for (int jj = 0; jj < 4; ++jj)
            atomicAdd(&g_T[(ty * 4 + ii) * 64 + (tx * 4 + jj)], acc[ii][jj]);
}

// ---------------------------------------------------------------------------
// Finalize: CE[i,j] = (S_i - T[i,j]) / 196 ; out = (trace/B) / (offdiag mean)
// ---------------------------------------------------------------------------
__global__ void k_final(float* __restrict__ out) {
    const int i = threadIdx.x;  // 64 threads
    const float s = g_S[i];
    float tot = 0.0f, diag = 0.0f;
    #pragma unroll 1
    for (int j = 0; j < 64; ++j) {
        const float ce = (s - g_T[i * 64 + j]) * (1.0f / (float)HW);
        tot += ce;
        if (j == i) diag = ce;
    }
    __shared__ float sd[64], st[64];
    sd[i] = diag; st[i] = tot; __syncthreads();
    #pragma unroll
    for (int k = 32; k > 0; k >>= 1) {
        if (i < k) { sd[i] += sd[i + k]; st[i] += st[i + k]; }
        __syncthreads();
    }
    if (i == 0) {
        const float dsum = sd[0], tsum = st[0];
        const float close = dsum / 64.0f;
        const float far   = (tsum - dsum) / (64.0f * 63.0f);
        out[0] = close / far;
    }
}

// ---------------------------------------------------------------------------
extern "C" void kernel_launch(void* const* d_in, const int* in_sizes, int n_in,
                              void* d_out, int out_size) {
    const float* x    = (const float*)d_in[0];  // (64,3,224,224)
    const float* y    = (const float*)d_in[1];  // (64,3,224,224)
    const float* W    = (const float*)d_in[2];  // (384,3,16,16)
    const float* bias = (const float*)d_in[3];  // (384,)
    float* out = (float*)d_out;

    k_init<<<17, 256>>>();
    k_patch_gemm<<<dim3(M_TOT / 64, HID / 64, 2), 256>>>(x, y, W, bias);
    k_softmax<<<dim3(M_TOT, 2), 128>>>();
    k_ce_gemm<<<KROW / 512, 256>>>();
    k_final<<<1, 64>>>(out);
}

// round 3
// speedup vs baseline: 1.4834x; 1.4834x over previous
#include <cuda_runtime.h>
#include <math.h>
#include <mma.h>
using namespace nvcuda;

// Problem constants
#define B_IMG 64
#define CH    3
#define IMG   224
#define IMG2  (IMG * IMG)
#define PATCH 16
#define HID   384
#define PW    14
#define HW    196
#define M_TOT (B_IMG * HW)        // 12544
#define K_PE  768                 // 3*16*16
#define KROW  (HW * HID)          // 75264

#define LDA 40                    // BK(32)+8 pad
#define LDB 40

// Scratch (device globals — no allocation allowed)
__device__ float g_emb[2u * M_TOT * HID]; // xp logits | yp logits -> q (in place)
__device__ float g_T[64 * 64];
__device__ float g_S[64];

// ---------------------------------------------------------------------------
__global__ void k_init() {
    int t = blockIdx.x * blockDim.x + threadIdx.x;
    if (t < 64 * 64) g_T[t] = 0.0f;
    if (t < 64)      g_S[t] = 0.0f;
}

// ---------------------------------------------------------------------------
// TF32 tensor-core patch-embed GEMM.
// out[m,n] = sum_k im2col[m,k] * W[n,k] + bias[n]
// BM=128, BN=64, BK=32; 8 warps as 4(M) x 2(N), 32x32 per warp (2x2 wmma).
// Bias is seeded into the accumulator via a staged bias tile.
// Grid: (N tiles=6, M tiles=98, 2 tensors) -> N-fastest so the 6 blocks that
// share one A stripe run adjacently (L2 reuse of the 393KB A stripe).
// ---------------------------------------------------------------------------
__global__ void __launch_bounds__(256)
k_patch_gemm_tc(const float* __restrict__ x, const float* __restrict__ y,
                const float* __restrict__ W, const float* __restrict__ bias) {
    __shared__ float As[128 * LDA];
    __shared__ float Bs[64 * LDB];
    __shared__ float biasS[16 * 72];

    const float* im  = blockIdx.z ? y : x;
    float*       out = g_emb + (size_t)blockIdx.z * (M_TOT * HID);
    const int n0 = blockIdx.x * 64;
    const int m0 = blockIdx.y * 128;

    const int t    = threadIdx.x;
    const int warp = t >> 5;
    const int wm   = warp >> 1;   // 0..3
    const int wn   = warp & 1;    // 0..1

    // Stage bias: 16 identical rows so accumulators can be seeded via wmma load.
    if (t < 64) {
        const float bv = bias[n0 + t];
        #pragma unroll
        for (int r = 0; r < 16; ++r) biasS[r * 72 + t] = bv;
    }
    __syncthreads();

    wmma::fragment<wmma::accumulator, 16, 16, 8, float> acc[2][2];
    #pragma unroll
    for (int i = 0; i < 2; ++i)
        #pragma unroll
        for (int j = 0; j < 2; ++j)
            wmma::load_matrix_sync(acc[i][j], &biasS[wn * 32 + j * 16], 72,
                                   wmma::mem_row_major);

    // Global load addressing. 256 threads: rowt = t/8 (0..31), qk = t%8 (float4 slot).
    const int qk   = t & 7;
    const int rowt = t >> 3;
    const float* aptr[4];
    #pragma unroll
    for (int i = 0; i < 4; ++i) {
        const int m   = m0 + rowt + i * 32;
        const int b   = m / HW;
        const int rem = m - b * HW;
        const int ph  = rem / PW;
        const int pw  = rem - ph * PW;
        aptr[i] = im + (size_t)b * (CH * IMG2)
                     + (size_t)(ph * PATCH + (qk >> 2)) * IMG
                     + pw * PATCH + (qk & 3) * 4;
    }
    const float* bptr[2];
    #pragma unroll
    for (int i = 0; i < 2; ++i)
        bptr[i] = W + (size_t)(n0 + rowt + i * 32) * K_PE + qk * 4;

    float* asm0 = &As[rowt * LDA + qk * 4];
    float* bsm0 = &Bs[rowt * LDB + qk * 4];

    #pragma unroll 1
    for (int kt = 0; kt < K_PE / 32; ++kt) {
        // k-tile -> (channel, patch-row-pair) offset in the image
        const int c  = kt >> 3;
        const int rb = (kt & 7) * 2;
        const long aoff = (long)c * IMG2 + rb * IMG;

        float4 av[4], bv[2];
        #pragma unroll
        for (int i = 0; i < 4; ++i) av[i] = *(const float4*)(aptr[i] + aoff);
        #pragma unroll
        for (int i = 0; i < 2; ++i) bv[i] = *(const float4*)(bptr[i] + kt * 32);

        __syncthreads();
        #pragma unroll
        for (int i = 0; i < 4; ++i) *(float4*)(asm0 + i * 32 * LDA) = av[i];
        #pragma unroll
        for (int i = 0; i < 2; ++i) *(float4*)(bsm0 + i * 32 * LDB) = bv[i];
        __syncthreads();

        #pragma unroll
        for (int kk = 0; kk < 4; ++kk) {
            wmma::fragment<wmma::matrix_a, 16, 16, 8, wmma::precision::tf32,
                           wmma::row_major> af[2];
            wmma::fragment<wmma::matrix_b, 16, 16, 8, wmma::precision::tf32,
                           wmma::col_major> bf[2];
            #pragma unroll
            for (int i = 0; i < 2; ++i) {
                wmma::load_matrix_sync(af[i], &As[(wm * 32 + i * 16) * LDA + kk * 8], LDA);
                #pragma unroll
                for (int e = 0; e < af[i].num_elements; ++e)
                    af[i].x[e] = wmma::__float_to_tf32(af[i].x[e]);
            }
            #pragma unroll
            for (int j = 0; j < 2; ++j) {
                wmma::load_matrix_sync(bf[j], &Bs[(wn * 32 + j * 16) * LDB + kk * 8], LDB);
                #pragma unroll
                for (int e = 0; e < bf[j].num_elements; ++e)
                    bf[j].x[e] = wmma::__float_to_tf32(bf[j].x[e]);
            }
            #pragma unroll
            for (int i = 0; i < 2; ++i)
                #pragma unroll
                for (int j = 0; j < 2; ++j)
                    wmma::mma_sync(acc[i][j], af[i], bf[j], acc[i][j]);
        }
    }

    #pragma unroll
    for (int i = 0; i < 2; ++i)
        #pragma unroll
        for (int j = 0; j < 2; ++j)
            wmma::store_matrix_sync(
                out + (size_t)(m0 + wm * 32 + i * 16) * HID + n0 + wn * 32 + j * 16,
                acc[i][j], HID, wmma::mem_row_major);
}

// ---------------------------------------------------------------------------
// Warp-per-row softmax. which==0: xp rows -> lse into S[i] (atomic).
//                       which==1: yp rows -> q = softmax(row), in place.
// 8 warps/block, 12 elements per lane (384 = 32*12).
// ---------------------------------------------------------------------------
__global__ void __launch_bounds__(256) k_softmax_w() {
    const int warp  = threadIdx.x >> 5;
    const int lane  = threadIdx.x & 31;
    const int row   = blockIdx.x * 8 + warp;
    const int which = blockIdx.y;
    float* p = g_emb + (size_t)which * (M_TOT * HID) + (size_t)row * HID;

    float v[12];
    #pragma unroll
    for (int j = 0; j < 12; ++j) v[j] = p[lane + j * 32];

    float mx = v[0];
    #pragma unroll
    for (int j = 1; j < 12; ++j) mx = fmaxf(mx, v[j]);
    #pragma unroll
    for (int s = 16; s > 0; s >>= 1)
        mx = fmaxf(mx, __shfl_xor_sync(0xffffffffu, mx, s));

    float sum = 0.0f;
    #pragma unroll
    for (int j = 0; j < 12; ++j) { v[j] = expf(v[j] - mx); sum += v[j]; }
    #pragma unroll
    for (int s = 16; s > 0; s >>= 1)
        sum += __shfl_xor_sync(0xffffffffu, sum, s);

    if (which == 1) {
        const float inv = 1.0f / sum;
        #pragma unroll
        for (int j = 0; j < 12; ++j) p[lane + j * 32] = v[j] * inv;
    } else {
        if (lane == 0) atomicAdd(&g_S[row / HW], mx + logf(sum));
    }
}

// ---------------------------------------------------------------------------
// CE GEMM: T[i,j] += sum_k XP[i,k]*Q[j,k]; split-K chunk 256 -> 294 blocks
// (2 CTAs/SM to cover load latency; R1's 147 blocks were latency-exposed).
// ---------------------------------------------------------------------------
__global__ void __launch_bounds__(256) k_ce_gemm() {
    __shared__ float As[16][68];
    __shared__ float Bs[16][68];

    const float* XP = g_emb;
    const float* Q  = g_emb + (size_t)M_TOT * HID;
    const int kbase = blockIdx.x * 256;

    const int t = threadIdx.x;
    const int lrow  = t >> 2;
    const int lquad = t & 3;
    const float* ap = XP + (size_t)lrow * KROW + kbase + lquad * 4;
    const float* bp = Q  + (size_t)lrow * KROW + kbase + lquad * 4;

    const int tx = t & 15;
    const int ty = t >> 4;
    float acc[4][4] = {};

    #pragma unroll 1
    for (int kt = 0; kt < 16; ++kt) {
        const float4 av = *(const float4*)(ap + kt * 16);
        const float4 bv = *(const float4*)(bp + kt * 16);
        __syncthreads();
        As[lquad * 4 + 0][lrow] = av.x;
        As[lquad * 4 + 1][lrow] = av.y;
        As[lquad * 4 + 2][lrow] = av.z;
        As[lquad * 4 + 3][lrow] = av.w;
        Bs[lquad * 4 + 0][lrow] = bv.x;
        Bs[lquad * 4 + 1][lrow] = bv.y;
        Bs[lquad * 4 + 2][lrow] = bv.z;
        Bs[lquad * 4 + 3][lrow] = bv.w;
        __syncthreads();
        #pragma unroll
        for (int k = 0; k < 16; ++k) {
            const float4 a4 = *(const float4*)&As[k][ty * 4];
            const float4 b4 = *(const float4*)&Bs[k][tx * 4];
            const float a[4]  = {a4.x, a4.y, a4.z, a4.w};
            const float bb[4] = {b4.x, b4.y, b4.z, b4.w};
            #pragma unroll
            for (int ii = 0; ii < 4; ++ii)
                #pragma unroll
                for (int jj = 0; jj < 4; ++jj)
                    acc[ii][jj] = fmaf(a[ii], bb[jj], acc[ii][jj]);
        }
    }

    #pragma unroll
    for (int ii = 0; ii < 4; ++ii)
        #pragma unroll
        for (int jj = 0; jj < 4; ++jj)
            atomicAdd(&g_T[(ty * 4 + ii) * 64 + (tx * 4 + jj)], acc[ii][jj]);
}

// ---------------------------------------------------------------------------
__global__ void k_final(float* __restrict__ out) {
    const int i = threadIdx.x;  // 64 threads
    const float s = g_S[i];
    float tot = 0.0f, diag = 0.0f;
    #pragma unroll 1
    for (int j = 0; j < 64; ++j) {
        const float ce = (s - g_T[i * 64 + j]) * (1.0f / (float)HW);
        tot += ce;
        if (j == i) diag = ce;
    }
    __shared__ float sd[64], st[64];
    sd[i] = diag; st[i] = tot; __syncthreads();
    #pragma unroll
    for (int k = 32; k > 0; k >>= 1) {
        if (i < k) { sd[i] += sd[i + k]; st[i] += st[i + k]; }
        __syncthreads();
    }
    if (i == 0) {
        const float dsum = sd[0], tsum = st[0];
        const float close = dsum / 64.0f;
        const float far   = (tsum - dsum) / (64.0f * 63.0f);
        out[0] = close / far;
    }
}

// ---------------------------------------------------------------------------
extern "C" void kernel_launch(void* const* d_in, const int* in_sizes, int n_in,
                              void* d_out, int out_size) {
    const float* x    = (const float*)d_in[0];
    const float* y    = (const float*)d_in[1];
    const float* W    = (const float*)d_in[2];
    const float* bias = (const float*)d_in[3];
    float* out = (float*)d_out;

    k_init<<<17, 256>>>();
    k_patch_gemm_tc<<<dim3(HID / 64, M_TOT / 128, 2), 256>>>(x, y, W, bias);
    k_softmax_w<<<dim3(M_TOT / 8, 2), 256>>>();
    k_ce_gemm<<<KROW / 256, 256>>>();
    k_final<<<1, 64>>>(out);
}